// round 5
// baseline (speedup 1.0000x reference)
#include <cuda_runtime.h>

#define NN     256
#define NS     512
#define MAXSP  32
#define NSTEPS 32
#define VRESET 1.0f
#define NT     256          // one neuron per thread
#define NWARP  (NT / 32)

__device__ __forceinline__ float sigmoidf_(float x) {
    float e = __expf(-x);
    return __fdividef(1.0f, 1.0f + e);
}

__global__ void __launch_bounds__(NT) snn_kernel(
    const float* __restrict__ input_current,  // [NN]
    const float* __restrict__ w,              // [NN, NN]
    const float* __restrict__ mu,             // [2]
    const float* __restrict__ v0,             // [NN]
    const float* __restrict__ i0,             // [NN]
    const float* __restrict__ s0,             // [NS, NN]
    const float* __restrict__ reset_s,        // [MAXSP, NS, NN]
    const int*   __restrict__ t1_raw,
    float* __restrict__ out_times,            // [NS, MAXSP]
    float* __restrict__ out_vals,             // [NS, MAXSP, NN, 3]
    float* __restrict__ out_marks)            // [NS, MAXSP, NN]
{
    const int s    = blockIdx.x;
    const int tid  = threadIdx.x;              // == neuron index
    const int wid  = tid >> 5;
    const int lane = tid & 31;
    const unsigned FULL = 0xffffffffu;

    __shared__ float    red_v[NWARP];
    __shared__ int      red_i[NWARP];
    __shared__ float    sp_sh, sn_sh;
    __shared__ unsigned ball[NWARP];

    // t1 dtype sniffing: small positive int -> integer payload; else float bits
    float t1f;
    {
        int iv = t1_raw[0];
        if (iv > 0 && iv < 1000000) t1f = (float)iv;
        else                        t1f = __int_as_float(iv);
    }

    const float m1 = mu[0];
    const float m2 = mu[1];

    const float ic = input_current[tid];
    float yv = v0[tid];
    float yi = i0[tid];
    float ys = s0[s * NN + tid];
    float t0s = 0.0f;

    for (int k = 0; k < MAXSP; ++k) {
        const float dt = (t1f - t0s) / (float)NSTEPS;
        const float h  = dt;
        const float hh = 0.5f * h;
        const float h6 = h / 6.0f;

        // ---- per-round affine RK4 coefficients (v,i are linear ODEs) ----
        // i-chain scalars
        const float i2c = 1.0f - hh * m2;
        const float i3c = 1.0f - hh * m2 * i2c;
        const float i4c = 1.0f - h  * m2 * i3c;
        const float Bi  = 1.0f - h6 * m2 * (1.0f + 2.0f * i2c + 2.0f * i3c + i4c);
        // v-chain coefficient triples over (v, i, ic)
        const float k1cv = -m1, k1ci = m1, k1cc = m1;
        const float v2cv = 1.0f + hh * k1cv, v2ci = hh * k1ci, v2cc = hh * k1cc;
        const float k2cv = -m1 * v2cv;
        const float k2ci = -m1 * v2ci + m1 * i2c;
        const float k2cc = -m1 * v2cc + m1;
        const float v3cv = 1.0f + hh * k2cv, v3ci = hh * k2ci, v3cc = hh * k2cc;
        const float k3cv = -m1 * v3cv;
        const float k3ci = -m1 * v3ci + m1 * i3c;
        const float k3cc = -m1 * v3cc + m1;
        const float v4cv = 1.0f + h * k3cv, v4ci = h * k3ci, v4cc = h * k3cc;
        const float k4cv = -m1 * v4cv;
        const float k4ci = -m1 * v4ci + m1 * i4c;
        const float k4cc = -m1 * v4cc + m1;
        const float Avv = 1.0f + h6 * (k1cv + 2.0f * k2cv + 2.0f * k3cv + k4cv);
        const float Avi =        h6 * (k1ci + 2.0f * k2ci + 2.0f * k3ci + k4ci);
        const float Avc =        h6 * (k1cc + 2.0f * k2cc + 2.0f * k3cc + k4cc);
        // fold ic into the constant terms (per neuron)
        const float v2K = v2cc * ic;
        const float v3K = v3cc * ic;
        const float v4K = v4cc * ic;
        const float nvK = Avc  * ic;

        float tev  = t1f;
        bool  trig = false;
        bool  em   = false;

        if (dt != 0.0f) {
            float t = t0s;
            for (int step = 0; step < NSTEPS; ++step) {
                // ---- affine RK4 step: short, wide dependency graph ----
                const float v2 = fmaf(v2cv, yv, fmaf(v2ci, yi, v2K));
                const float v3 = fmaf(v3cv, yv, fmaf(v3ci, yi, v3K));
                const float v4 = fmaf(v4cv, yv, fmaf(v4ci, yi, v4K));
                const float s1 = sigmoidf_(yv);
                const float s2 = sigmoidf_(v2);
                const float s3 = sigmoidf_(v3);
                const float s4 = sigmoidf_(v4);
                const float nv = fmaf(Avv, yv, fmaf(Avi, yi, nvK));
                const float ni = Bi * yi;
                const float ns = ys + h6 * (s1 + 2.0f * s2 + 2.0f * s3 + s4);

                // single hardware BAR.RED per step — trigger fast path
                if (__syncthreads_or(ns > 0.0f)) {
                    // ---- full argmax(s_new), first-index tie-break ----
                    float bv = ns; int bi = tid;
                    #pragma unroll
                    for (int o = 16; o > 0; o >>= 1) {
                        float ov = __shfl_xor_sync(FULL, bv, o);
                        int   oi = __shfl_xor_sync(FULL, bi, o);
                        if (ov > bv || (ov == bv && oi < bi)) { bv = ov; bi = oi; }
                    }
                    if (lane == 0) { red_v[wid] = bv; red_i[wid] = bi; }
                    __syncthreads();
                    float mv = red_v[0]; int mi = red_i[0];
                    #pragma unroll
                    for (int ww = 1; ww < NWARP; ++ww) {
                        float ov = red_v[ww]; int oi = red_i[ww];
                        if (ov > mv || (ov == mv && oi < mi)) { mv = ov; mi = oi; }
                    }
                    if (tid == mi) { sp_sh = ys; sn_sh = ns; }
                    __syncthreads();
                    const float sp = sp_sh, sn = sn_sh;
                    float frac = sp / (sp - sn + 1e-12f);
                    frac = fminf(fmaxf(frac, 0.0f), 1.0f);
                    tev = t + frac * dt;
                    yv  = yv + frac * (nv - yv);
                    yi  = yi + frac * (ni - yi);
                    ys  = ys + frac * (ns - ys);
                    em  = (ns > 0.0f);
                    trig = true;
                    break;
                }
                yv = nv; yi = ni; ys = ns;
                t += dt;
            }
        }

        // ---- outputs (event state = current y) ----
        if (tid == 0) out_times[s * MAXSP + k] = tev;
        const long row  = (long)(s * MAXSP + k);
        const long base = (row * NN + tid) * 3;
        out_vals[base + 0] = yv;
        out_vals[base + 1] = yi;
        out_vals[base + 2] = ys;
        out_marks[row * NN + tid] = em ? 1.0f : 0.0f;

        // ---- next-round state ----
        if (trig) {
            unsigned b = __ballot_sync(FULL, em);
            if (lane == 0) ball[wid] = b;
            __syncthreads();
            int eidx = 0;
            #pragma unroll
            for (int ww = 0; ww < NWARP; ++ww) {
                unsigned bb = ball[ww];
                if (bb) { eidx = ww * 32 + __ffs(bb) - 1; break; }
            }
            yv = yv - (em ? VRESET : 0.0f);
            yi = yi + w[eidx * NN + tid];
            const float rs = reset_s[((long)k * NS + s) * NN + tid];
            ys = fminf(em ? rs : ys, 0.0f);
        } else {
            ys = fminf(ys, 0.0f);
        }
        t0s = tev;
        __syncthreads();   // smem reuse guard across rounds (uniform)
    }
}

extern "C" void kernel_launch(void* const* d_in, const int* in_sizes, int n_in,
                              void* d_out, int out_size) {
    const float* input_current = (const float*)d_in[0];
    const float* w             = (const float*)d_in[1];
    const float* mu            = (const float*)d_in[2];
    const float* v0            = (const float*)d_in[3];
    const float* i0            = (const float*)d_in[4];
    const float* s0            = (const float*)d_in[5];
    const float* reset_s       = (const float*)d_in[6];
    const int*   t1            = (const int*)  d_in[7];

    float* out = (float*)d_out;
    float* out_times = out;                                      // 512*32
    float* out_vals  = out + (long)NS * MAXSP;                   // 512*32*256*3
    float* out_marks = out + (long)NS * MAXSP
                           + (long)NS * MAXSP * NN * 3;          // 512*32*256

    snn_kernel<<<NS, NT>>>(input_current, w, mu, v0, i0, s0, reset_s, t1,
                           out_times, out_vals, out_marks);
}

// round 8
// speedup vs baseline: 1.4487x; 1.4487x over previous
#include <cuda_runtime.h>

#define NN     256
#define NS     512
#define MAXSP  32
#define NSTEPS 32
#define VRESET 1.0f
#define JPT    2            // neurons per thread
#define NT     128          // threads per block
#define NWARP  (NT / 32)

__device__ __forceinline__ float sigmoidf_(float x) {
    float e = __expf(-x);
    return __fdividef(1.0f, 1.0f + e);
}

__global__ void __launch_bounds__(NT) snn_kernel(
    const float* __restrict__ input_current,  // [NN]
    const float* __restrict__ w,              // [NN, NN]
    const float* __restrict__ mu,             // [2]
    const float* __restrict__ v0,             // [NN]
    const float* __restrict__ i0,             // [NN]
    const float* __restrict__ s0,             // [NS, NN]
    const float* __restrict__ reset_s,        // [MAXSP, NS, NN]
    const int*   __restrict__ t1_raw,
    float* __restrict__ out_times,            // [NS, MAXSP]
    float* __restrict__ out_vals,             // [NS, MAXSP, NN, 3]
    float* __restrict__ out_marks)            // [NS, MAXSP, NN]
{
    const int s    = blockIdx.x;
    const int tid  = threadIdx.x;
    const int wid  = tid >> 5;
    const int lane = tid & 31;
    const unsigned FULL = 0xffffffffu;

    __shared__ float    red_v[NWARP];
    __shared__ int      red_i[NWARP];
    __shared__ float    sp_sh, sn_sh;
    __shared__ unsigned ball[JPT * NWARP];

    // t1 dtype sniffing: small positive int -> integer payload; else float bits
    float t1f;
    {
        int iv = t1_raw[0];
        if (iv > 0 && iv < 1000000) t1f = (float)iv;
        else                        t1f = __int_as_float(iv);
    }

    const float m1 = mu[0];
    const float m2 = mu[1];

    // neuron indices: n_j = tid + j*NT (coalesced)
    float ic[JPT], yv[JPT], yi[JPT], ys[JPT];
    #pragma unroll
    for (int j = 0; j < JPT; ++j) {
        const int n = tid + j * NT;
        ic[j] = input_current[n];
        yv[j] = v0[n];
        yi[j] = i0[n];
        ys[j] = s0[s * NN + n];
    }
    float t0s = 0.0f;

    for (int k = 0; k < MAXSP; ++k) {
        const float dt = (t1f - t0s) / (float)NSTEPS;
        const float h  = dt;
        const float hh = 0.5f * h;
        const float h6 = h / 6.0f;

        // ---- per-round affine RK4 coefficients (v,i are linear ODEs) ----
        const float i2c = 1.0f - hh * m2;
        const float i3c = 1.0f - hh * m2 * i2c;
        const float i4c = 1.0f - h  * m2 * i3c;
        const float Bi  = 1.0f - h6 * m2 * (1.0f + 2.0f * i2c + 2.0f * i3c + i4c);
        const float k1cv = -m1, k1ci = m1, k1cc = m1;
        const float v2cv = 1.0f + hh * k1cv, v2ci = hh * k1ci, v2cc = hh * k1cc;
        const float k2cv = -m1 * v2cv;
        const float k2ci = -m1 * v2ci + m1 * i2c;
        const float k2cc = -m1 * v2cc + m1;
        const float v3cv = 1.0f + hh * k2cv, v3ci = hh * k2ci, v3cc = hh * k2cc;
        const float k3cv = -m1 * v3cv;
        const float k3ci = -m1 * v3ci + m1 * i3c;
        const float k3cc = -m1 * v3cc + m1;
        const float v4cv = 1.0f + h * k3cv, v4ci = h * k3ci, v4cc = h * k3cc;
        const float k4cv = -m1 * v4cv;
        const float k4ci = -m1 * v4ci + m1 * i4c;
        const float k4cc = -m1 * v4cc + m1;
        const float Avv = 1.0f + h6 * (k1cv + 2.0f * k2cv + 2.0f * k3cv + k4cv);
        const float Avi =        h6 * (k1ci + 2.0f * k2ci + 2.0f * k3ci + k4ci);
        const float Avc =        h6 * (k1cc + 2.0f * k2cc + 2.0f * k3cc + k4cc);
        float v2K[JPT], v3K[JPT], v4K[JPT], nvK[JPT];
        #pragma unroll
        for (int j = 0; j < JPT; ++j) {
            v2K[j] = v2cc * ic[j];
            v3K[j] = v3cc * ic[j];
            v4K[j] = v4cc * ic[j];
            nvK[j] = Avc  * ic[j];
        }

        float tev  = t1f;
        bool  trig = false;
        int   emask = 0;       // bit j: neuron tid + j*NT crossed at event

        if (dt != 0.0f) {
            float t = t0s;
            for (int step = 0; step < NSTEPS; ++step) {
                float nv[JPT], ni[JPT], ns[JPT];
                int anyl = 0;
                #pragma unroll
                for (int j = 0; j < JPT; ++j) {
                    // ---- affine RK4 step: short, wide dependency graph ----
                    const float v2 = fmaf(v2cv, yv[j], fmaf(v2ci, yi[j], v2K[j]));
                    const float v3 = fmaf(v3cv, yv[j], fmaf(v3ci, yi[j], v3K[j]));
                    const float v4 = fmaf(v4cv, yv[j], fmaf(v4ci, yi[j], v4K[j]));
                    const float s1 = sigmoidf_(yv[j]);
                    const float s2 = sigmoidf_(v2);
                    const float s3 = sigmoidf_(v3);
                    const float s4 = sigmoidf_(v4);
                    nv[j] = fmaf(Avv, yv[j], fmaf(Avi, yi[j], nvK[j]));
                    ni[j] = Bi * yi[j];
                    ns[j] = ys[j] + h6 * (s1 + 2.0f * s2 + 2.0f * s3 + s4);
                    anyl |= (ns[j] > 0.0f) ? 1 : 0;
                }

                // single hardware BAR.RED per step — trigger fast path
                if (__syncthreads_or(anyl)) {
                    // ---- full argmax(s_new), first-index tie-break ----
                    float bv = ns[0]; int bi = tid;
                    #pragma unroll
                    for (int j = 1; j < JPT; ++j) {
                        const int nj = tid + j * NT;
                        if (ns[j] > bv || (ns[j] == bv && nj < bi)) { bv = ns[j]; bi = nj; }
                    }
                    #pragma unroll
                    for (int o = 16; o > 0; o >>= 1) {
                        float ov = __shfl_xor_sync(FULL, bv, o);
                        int   oi = __shfl_xor_sync(FULL, bi, o);
                        if (ov > bv || (ov == bv && oi < bi)) { bv = ov; bi = oi; }
                    }
                    if (lane == 0) { red_v[wid] = bv; red_i[wid] = bi; }
                    __syncthreads();
                    float mv = red_v[0]; int mi = red_i[0];
                    #pragma unroll
                    for (int ww = 1; ww < NWARP; ++ww) {
                        float ov = red_v[ww]; int oi = red_i[ww];
                        if (ov > mv || (ov == mv && oi < mi)) { mv = ov; mi = oi; }
                    }
                    #pragma unroll
                    for (int j = 0; j < JPT; ++j) {
                        if (tid + j * NT == mi) { sp_sh = ys[j]; sn_sh = ns[j]; }
                    }
                    __syncthreads();
                    const float sp = sp_sh, sn = sn_sh;
                    float frac = sp / (sp - sn + 1e-12f);
                    frac = fminf(fmaxf(frac, 0.0f), 1.0f);
                    tev = t + frac * dt;
                    #pragma unroll
                    for (int j = 0; j < JPT; ++j) {
                        yv[j] = yv[j] + frac * (nv[j] - yv[j]);
                        yi[j] = yi[j] + frac * (ni[j] - yi[j]);
                        ys[j] = ys[j] + frac * (ns[j] - ys[j]);
                        if (ns[j] > 0.0f) emask |= (1 << j);
                    }
                    trig = true;
                    break;
                }
                #pragma unroll
                for (int j = 0; j < JPT; ++j) { yv[j] = nv[j]; yi[j] = ni[j]; ys[j] = ns[j]; }
                t += dt;
            }
        }

        // ---- outputs (event state = current y) ----
        if (tid == 0) out_times[s * MAXSP + k] = tev;
        const long row = (long)(s * MAXSP + k);
        #pragma unroll
        for (int j = 0; j < JPT; ++j) {
            const int n = tid + j * NT;
            const long base = (row * NN + n) * 3;
            out_vals[base + 0] = yv[j];
            out_vals[base + 1] = yi[j];
            out_vals[base + 2] = ys[j];
            out_marks[row * NN + n] = (emask >> j) & 1 ? 1.0f : 0.0f;
        }

        // ---- next-round state ----
        if (trig) {
            #pragma unroll
            for (int j = 0; j < JPT; ++j) {
                unsigned b = __ballot_sync(FULL, (emask >> j) & 1);
                if (lane == 0) ball[j * NWARP + wid] = b;
            }
            __syncthreads();
            int eidx = 0;
            #pragma unroll
            for (int q = 0; q < JPT * NWARP; ++q) {
                unsigned bb = ball[q];
                if (bb) { eidx = (q / NWARP) * NT + (q % NWARP) * 32 + __ffs(bb) - 1; break; }
            }
            #pragma unroll
            for (int j = 0; j < JPT; ++j) {
                const int n = tid + j * NT;
                const bool em = (emask >> j) & 1;
                yv[j] = yv[j] - (em ? VRESET : 0.0f);
                yi[j] = yi[j] + w[eidx * NN + n];
                const float rs = reset_s[((long)k * NS + s) * NN + n];
                ys[j] = fminf(em ? rs : ys[j], 0.0f);
            }
        } else {
            #pragma unroll
            for (int j = 0; j < JPT; ++j) ys[j] = fminf(ys[j], 0.0f);
        }
        t0s = tev;
        __syncthreads();   // smem reuse guard across rounds (uniform)
    }
}

extern "C" void kernel_launch(void* const* d_in, const int* in_sizes, int n_in,
                              void* d_out, int out_size) {
    const float* input_current = (const float*)d_in[0];
    const float* w             = (const float*)d_in[1];
    const float* mu            = (const float*)d_in[2];
    const float* v0            = (const float*)d_in[3];
    const float* i0            = (const float*)d_in[4];
    const float* s0            = (const float*)d_in[5];
    const float* reset_s       = (const float*)d_in[6];
    const int*   t1            = (const int*)  d_in[7];

    float* out = (float*)d_out;
    float* out_times = out;                                      // 512*32
    float* out_vals  = out + (long)NS * MAXSP;                   // 512*32*256*3
    float* out_marks = out + (long)NS * MAXSP
                           + (long)NS * MAXSP * NN * 3;          // 512*32*256

    snn_kernel<<<NS, NT>>>(input_current, w, mu, v0, i0, s0, reset_s, t1,
                           out_times, out_vals, out_marks);
}

// round 10
// speedup vs baseline: 1.5169x; 1.0471x over previous
#include <cuda_runtime.h>

#define NN     256
#define NS     512
#define MAXSP  32
#define NSTEPS 32
#define VRESET 1.0f
#define JPT    2            // neurons per thread
#define NT     128          // threads per block
#define NWARP  (NT / 32)

__device__ __forceinline__ float sigmoidf_(float x) {
    float e = __expf(-x);
    return __fdividef(1.0f, 1.0f + e);
}

__global__ void __launch_bounds__(NT) snn_kernel(
    const float* __restrict__ input_current,  // [NN]
    const float* __restrict__ w,              // [NN, NN]
    const float* __restrict__ mu,             // [2]
    const float* __restrict__ v0,             // [NN]
    const float* __restrict__ i0,             // [NN]
    const float* __restrict__ s0,             // [NS, NN]
    const float* __restrict__ reset_s,        // [MAXSP, NS, NN]
    const int*   __restrict__ t1_raw,
    float* __restrict__ out_times,            // [NS, MAXSP]
    float* __restrict__ out_vals,             // [NS, MAXSP, NN, 3]
    float* __restrict__ out_marks)            // [NS, MAXSP, NN]
{
    const int s    = blockIdx.x;
    const int tid  = threadIdx.x;
    const int wid  = tid >> 5;
    const int lane = tid & 31;
    const unsigned FULL = 0xffffffffu;

    __shared__ float    red_v[NWARP];
    __shared__ int      red_i[NWARP];
    __shared__ float    red_sp[NWARP];
    __shared__ float    red_sn[NWARP];
    __shared__ unsigned ball[JPT * NWARP];

    // t1 dtype sniffing: small positive int -> integer payload; else float bits
    float t1f;
    {
        int iv = t1_raw[0];
        if (iv > 0 && iv < 1000000) t1f = (float)iv;
        else                        t1f = __int_as_float(iv);
    }

    const float m1 = mu[0];
    const float m2 = mu[1];

    // neuron indices: n_j = tid + j*NT (coalesced)
    float ic[JPT], yv[JPT], yi[JPT], ys[JPT];
    #pragma unroll
    for (int j = 0; j < JPT; ++j) {
        const int n = tid + j * NT;
        ic[j] = input_current[n];
        yv[j] = v0[n];
        yi[j] = i0[n];
        ys[j] = s0[s * NN + n];
    }
    float t0s = 0.0f;

    for (int k = 0; k < MAXSP; ++k) {
        // ---- prefetch this round's reset row EARLY (DRAM latency hidden
        //      behind the whole round's compute; consumed at round end) ----
        float rs_pref[JPT];
        #pragma unroll
        for (int j = 0; j < JPT; ++j)
            rs_pref[j] = __ldg(&reset_s[((long)k * NS + s) * NN + tid + j * NT]);

        const float dt = (t1f - t0s) / (float)NSTEPS;
        const float h  = dt;
        const float hh = 0.5f * h;
        const float h6 = h / 6.0f;

        // ---- per-round affine RK4 coefficients (v,i are linear ODEs) ----
        const float i2c = 1.0f - hh * m2;
        const float i3c = 1.0f - hh * m2 * i2c;
        const float i4c = 1.0f - h  * m2 * i3c;
        const float Bi  = 1.0f - h6 * m2 * (1.0f + 2.0f * i2c + 2.0f * i3c + i4c);
        const float k1cv = -m1, k1ci = m1, k1cc = m1;
        const float v2cv = 1.0f + hh * k1cv, v2ci = hh * k1ci, v2cc = hh * k1cc;
        const float k2cv = -m1 * v2cv;
        const float k2ci = -m1 * v2ci + m1 * i2c;
        const float k2cc = -m1 * v2cc + m1;
        const float v3cv = 1.0f + hh * k2cv, v3ci = hh * k2ci, v3cc = hh * k2cc;
        const float k3cv = -m1 * v3cv;
        const float k3ci = -m1 * v3ci + m1 * i3c;
        const float k3cc = -m1 * v3cc + m1;
        const float v4cv = 1.0f + h * k3cv, v4ci = h * k3ci, v4cc = h * k3cc;
        const float k4cv = -m1 * v4cv;
        const float k4ci = -m1 * v4ci + m1 * i4c;
        const float k4cc = -m1 * v4cc + m1;
        const float Avv = 1.0f + h6 * (k1cv + 2.0f * k2cv + 2.0f * k3cv + k4cv);
        const float Avi =        h6 * (k1ci + 2.0f * k2ci + 2.0f * k3ci + k4ci);
        const float Avc =        h6 * (k1cc + 2.0f * k2cc + 2.0f * k3cc + k4cc);
        float v2K[JPT], v3K[JPT], v4K[JPT], nvK[JPT];
        #pragma unroll
        for (int j = 0; j < JPT; ++j) {
            v2K[j] = v2cc * ic[j];
            v3K[j] = v3cc * ic[j];
            v4K[j] = v4cc * ic[j];
            nvK[j] = Avc  * ic[j];
        }

        float tev  = t1f;
        bool  trig = false;
        int   emask = 0;       // bit j: neuron tid + j*NT crossed at event

        if (dt != 0.0f) {
            float t = t0s;
            for (int step = 0; step < NSTEPS; ++step) {
                float nv[JPT], ni[JPT], ns[JPT];
                int anyl = 0;
                #pragma unroll
                for (int j = 0; j < JPT; ++j) {
                    // ---- affine RK4 step: short, wide dependency graph ----
                    const float v2 = fmaf(v2cv, yv[j], fmaf(v2ci, yi[j], v2K[j]));
                    const float v3 = fmaf(v3cv, yv[j], fmaf(v3ci, yi[j], v3K[j]));
                    const float v4 = fmaf(v4cv, yv[j], fmaf(v4ci, yi[j], v4K[j]));
                    const float s1 = sigmoidf_(yv[j]);
                    const float s2 = sigmoidf_(v2);
                    const float s3 = sigmoidf_(v3);
                    const float s4 = sigmoidf_(v4);
                    nv[j] = fmaf(Avv, yv[j], fmaf(Avi, yi[j], nvK[j]));
                    ni[j] = Bi * yi[j];
                    ns[j] = ys[j] + h6 * (s1 + 2.0f * s2 + 2.0f * s3 + s4);
                    anyl |= (ns[j] > 0.0f) ? 1 : 0;
                }

                // single hardware BAR.RED per step — trigger fast path
                if (__syncthreads_or(anyl)) {
                    // ---- fused trigger path: ballots + per-warp argmax tuple
                    //      published together -> ONE barrier ----
                    #pragma unroll
                    for (int j = 0; j < JPT; ++j) {
                        unsigned b = __ballot_sync(FULL, ns[j] > 0.0f);
                        if (lane == 0) ball[j * NWARP + wid] = b;
                    }
                    float bv = ns[0]; int bi = tid;
                    #pragma unroll
                    for (int j = 1; j < JPT; ++j) {
                        const int nj = tid + j * NT;
                        if (ns[j] > bv || (ns[j] == bv && nj < bi)) { bv = ns[j]; bi = nj; }
                    }
                    #pragma unroll
                    for (int o = 16; o > 0; o >>= 1) {
                        float ov = __shfl_xor_sync(FULL, bv, o);
                        int   oi = __shfl_xor_sync(FULL, bi, o);
                        if (ov > bv || (ov == bv && oi < bi)) { bv = ov; bi = oi; }
                    }
                    // warp-winner owner publishes value, index, and its (sp, sn)
                    if ((bi & (NT - 1)) == tid) {
                        const int jw = bi >> 7;   // bi / NT
                        red_v[wid]  = bv;
                        red_i[wid]  = bi;
                        red_sp[wid] = (jw == 0) ? ys[0] : ys[JPT - 1];
                        red_sn[wid] = (jw == 0) ? ns[0] : ns[JPT - 1];
                    }
                    __syncthreads();
                    float mv = red_v[0]; int mi = red_i[0];
                    float sp = red_sp[0], sn = red_sn[0];
                    #pragma unroll
                    for (int ww = 1; ww < NWARP; ++ww) {
                        float ov = red_v[ww]; int oi = red_i[ww];
                        if (ov > mv || (ov == mv && oi < mi)) {
                            mv = ov; mi = oi; sp = red_sp[ww]; sn = red_sn[ww];
                        }
                    }
                    float frac = sp / (sp - sn + 1e-12f);
                    frac = fminf(fmaxf(frac, 0.0f), 1.0f);
                    tev = t + frac * dt;
                    #pragma unroll
                    for (int j = 0; j < JPT; ++j) {
                        yv[j] = yv[j] + frac * (nv[j] - yv[j]);
                        yi[j] = yi[j] + frac * (ni[j] - yi[j]);
                        ys[j] = ys[j] + frac * (ns[j] - ys[j]);
                        if (ns[j] > 0.0f) emask |= (1 << j);
                    }
                    trig = true;
                    break;
                }
                #pragma unroll
                for (int j = 0; j < JPT; ++j) { yv[j] = nv[j]; yi[j] = ni[j]; ys[j] = ns[j]; }
                t += dt;
            }
        }

        // ---- outputs (event state = current y) ----
        if (tid == 0) out_times[s * MAXSP + k] = tev;
        const long row = (long)(s * MAXSP + k);
        #pragma unroll
        for (int j = 0; j < JPT; ++j) {
            const int n = tid + j * NT;
            const long base = (row * NN + n) * 3;
            out_vals[base + 0] = yv[j];
            out_vals[base + 1] = yi[j];
            out_vals[base + 2] = ys[j];
            out_marks[row * NN + n] = (emask >> j) & 1 ? 1.0f : 0.0f;
        }

        // ---- next-round state ----
        if (trig) {
            // eidx = first neuron index with event mark (ball[] written pre-barrier)
            int eidx = 0;
            #pragma unroll
            for (int q = 0; q < JPT * NWARP; ++q) {
                unsigned bb = ball[q];
                if (bb) { eidx = (q / NWARP) * NT + (q % NWARP) * 32 + __ffs(bb) - 1; break; }
            }
            #pragma unroll
            for (int j = 0; j < JPT; ++j) {
                const int n = tid + j * NT;
                const bool em = (emask >> j) & 1;
                yv[j] = yv[j] - (em ? VRESET : 0.0f);
                yi[j] = yi[j] + w[eidx * NN + n];
                ys[j] = fminf(em ? rs_pref[j] : ys[j], 0.0f);
            }
        } else {
            #pragma unroll
            for (int j = 0; j < JPT; ++j) ys[j] = fminf(ys[j], 0.0f);
        }
        t0s = tev;
        // no trailing barrier: the next round's first __syncthreads_or orders
        // all smem reuse (writes only occur after a barrier everyone passed)
    }
}

extern "C" void kernel_launch(void* const* d_in, const int* in_sizes, int n_in,
                              void* d_out, int out_size) {
    const float* input_current = (const float*)d_in[0];
    const float* w             = (const float*)d_in[1];
    const float* mu            = (const float*)d_in[2];
    const float* v0            = (const float*)d_in[3];
    const float* i0            = (const float*)d_in[4];
    const float* s0            = (const float*)d_in[5];
    const float* reset_s       = (const float*)d_in[6];
    const int*   t1            = (const int*)  d_in[7];

    float* out = (float*)d_out;
    float* out_times = out;                                      // 512*32
    float* out_vals  = out + (long)NS * MAXSP;                   // 512*32*256*3
    float* out_marks = out + (long)NS * MAXSP
                           + (long)NS * MAXSP * NN * 3;          // 512*32*256

    snn_kernel<<<NS, NT>>>(input_current, w, mu, v0, i0, s0, reset_s, t1,
                           out_times, out_vals, out_marks);
}

// round 11
// speedup vs baseline: 1.5180x; 1.0007x over previous
#include <cuda_runtime.h>

#define NN     256
#define NS     512
#define MAXSP  32
#define NSTEPS 32
#define VRESET 1.0f
#define JPT    2            // neurons per thread
#define NT     128          // threads per block
#define NWARP  (NT / 32)

__device__ __forceinline__ float sigmoidf_(float x) {
    float e = __expf(-x);
    return __fdividef(1.0f, 1.0f + e);
}

// monotonic float -> u32 key: a > b  <=>  fkey(a) > fkey(b)
__device__ __forceinline__ unsigned fkey(float f) {
    unsigned u = __float_as_uint(f);
    return ((int)u < 0) ? ~u : (u | 0x80000000u);
}

__global__ void __launch_bounds__(NT) snn_kernel(
    const float* __restrict__ input_current,  // [NN]
    const float* __restrict__ w,              // [NN, NN]
    const float* __restrict__ mu,             // [2]
    const float* __restrict__ v0,             // [NN]
    const float* __restrict__ i0,             // [NN]
    const float* __restrict__ s0,             // [NS, NN]
    const float* __restrict__ reset_s,        // [MAXSP, NS, NN]
    const int*   __restrict__ t1_raw,
    float* __restrict__ out_times,            // [NS, MAXSP]
    float* __restrict__ out_vals,             // [NS, MAXSP, NN, 3]
    float* __restrict__ out_marks)            // [NS, MAXSP, NN]
{
    const int s    = blockIdx.x;
    const int tid  = threadIdx.x;
    const int wid  = tid >> 5;
    const int lane = tid & 31;
    const unsigned FULL = 0xffffffffu;

    __shared__ uint4    red[NWARP];           // {key, bi, sp_bits, sn_bits}
    __shared__ unsigned ball[JPT * NWARP];

    // t1 dtype sniffing: small positive int -> integer payload; else float bits
    float t1f;
    {
        int iv = t1_raw[0];
        if (iv > 0 && iv < 1000000) t1f = (float)iv;
        else                        t1f = __int_as_float(iv);
    }

    const float m1 = mu[0];
    const float m2 = mu[1];

    // neuron indices: n_j = tid + j*NT (coalesced)
    float ic[JPT], yv[JPT], yi[JPT], ys[JPT];
    #pragma unroll
    for (int j = 0; j < JPT; ++j) {
        const int n = tid + j * NT;
        ic[j] = input_current[n];
        yv[j] = v0[n];
        yi[j] = i0[n];
        ys[j] = s0[s * NN + n];
    }
    float t0s = 0.0f;

    // software-pipelined reset_s: rs_cur holds round k's row
    float rs_cur[JPT], rs_nxt[JPT];
    #pragma unroll
    for (int j = 0; j < JPT; ++j)
        rs_cur[j] = __ldg(&reset_s[(long)s * NN + tid + j * NT]);   // k = 0

    for (int k = 0; k < MAXSP; ++k) {
        // prefetch NEXT round's reset row (full round of latency cover)
        if (k + 1 < MAXSP) {
            #pragma unroll
            for (int j = 0; j < JPT; ++j)
                rs_nxt[j] = __ldg(&reset_s[((long)(k + 1) * NS + s) * NN + tid + j * NT]);
        }

        const float dt = (t1f - t0s) / (float)NSTEPS;
        const float h  = dt;
        const float hh = 0.5f * h;
        const float h6 = h / 6.0f;

        // ---- per-round affine RK4 coefficients (v,i are linear ODEs) ----
        const float i2c = 1.0f - hh * m2;
        const float i3c = 1.0f - hh * m2 * i2c;
        const float i4c = 1.0f - h  * m2 * i3c;
        const float Bi  = 1.0f - h6 * m2 * (1.0f + 2.0f * i2c + 2.0f * i3c + i4c);
        const float k1cv = -m1, k1ci = m1, k1cc = m1;
        const float v2cv = 1.0f + hh * k1cv, v2ci = hh * k1ci, v2cc = hh * k1cc;
        const float k2cv = -m1 * v2cv;
        const float k2ci = -m1 * v2ci + m1 * i2c;
        const float k2cc = -m1 * v2cc + m1;
        const float v3cv = 1.0f + hh * k2cv, v3ci = hh * k2ci, v3cc = hh * k2cc;
        const float k3cv = -m1 * v3cv;
        const float k3ci = -m1 * v3ci + m1 * i3c;
        const float k3cc = -m1 * v3cc + m1;
        const float v4cv = 1.0f + h * k3cv, v4ci = h * k3ci, v4cc = h * k3cc;
        const float k4cv = -m1 * v4cv;
        const float k4ci = -m1 * v4ci + m1 * i4c;
        const float k4cc = -m1 * v4cc + m1;
        const float Avv = 1.0f + h6 * (k1cv + 2.0f * k2cv + 2.0f * k3cv + k4cv);
        const float Avi =        h6 * (k1ci + 2.0f * k2ci + 2.0f * k3ci + k4ci);
        const float Avc =        h6 * (k1cc + 2.0f * k2cc + 2.0f * k3cc + k4cc);
        float v2K[JPT], v3K[JPT], v4K[JPT], nvK[JPT];
        #pragma unroll
        for (int j = 0; j < JPT; ++j) {
            v2K[j] = v2cc * ic[j];
            v3K[j] = v3cc * ic[j];
            v4K[j] = v4cc * ic[j];
            nvK[j] = Avc  * ic[j];
        }

        float tev  = t1f;
        bool  trig = false;
        int   emask = 0;       // bit j: neuron tid + j*NT crossed at event

        if (dt != 0.0f) {
            float t = t0s;
            for (int step = 0; step < NSTEPS; ++step) {
                float nv[JPT], ni[JPT], ns[JPT];
                int anyl = 0;
                #pragma unroll
                for (int j = 0; j < JPT; ++j) {
                    // ---- affine RK4 step: short, wide dependency graph ----
                    const float v2 = fmaf(v2cv, yv[j], fmaf(v2ci, yi[j], v2K[j]));
                    const float v3 = fmaf(v3cv, yv[j], fmaf(v3ci, yi[j], v3K[j]));
                    const float v4 = fmaf(v4cv, yv[j], fmaf(v4ci, yi[j], v4K[j]));
                    const float s1 = sigmoidf_(yv[j]);
                    const float s2 = sigmoidf_(v2);
                    const float s3 = sigmoidf_(v3);
                    const float s4 = sigmoidf_(v4);
                    nv[j] = fmaf(Avv, yv[j], fmaf(Avi, yi[j], nvK[j]));
                    ni[j] = Bi * yi[j];
                    ns[j] = ys[j] + h6 * (s1 + 2.0f * s2 + 2.0f * s3 + s4);
                    anyl |= (ns[j] > 0.0f) ? 1 : 0;
                }

                // single hardware BAR.RED per step — trigger fast path
                if (__syncthreads_or(anyl)) {
                    // ---- crossed ballots (also feed eidx scan post-barrier) ----
                    unsigned em0 = __ballot_sync(FULL, ns[0] > 0.0f);
                    unsigned em1 = __ballot_sync(FULL, ns[1] > 0.0f);
                    if (lane == 0) { ball[wid] = em0; ball[NWARP + wid] = em1; }

                    // guaranteed-correct L1 prefetch of this warp's first-crossed
                    // row: block eidx is the min over warp firsts, and L1 is
                    // SM-shared, so the winning row is always prefetched.
                    int cand = -1;
                    if (em0)      cand = wid * 32 + __ffs(em0) - 1;
                    else if (em1) cand = NT + wid * 32 + __ffs(em1) - 1;
                    if (cand >= 0 && lane < 8)
                        asm volatile("prefetch.global.L1 [%0];"
                                     :: "l"(&w[cand * NN + lane * 32]));

                    // ---- exact argmax via REDUX on monotonic key ----
                    const unsigned key0 = fkey(ns[0]);
                    const unsigned key1 = fkey(ns[1]);
                    unsigned kb; int bj;
                    if (key1 > key0) { kb = key1; bj = 1; }
                    else             { kb = key0; bj = 0; }
                    const unsigned wmax = __reduce_max_sync(FULL, kb);
                    // owner: smallest neuron index among lanes at wmax
                    unsigned b0 = __ballot_sync(FULL, (kb == wmax) && (bj == 0));
                    int wlane, wbi;
                    if (b0) { wlane = __ffs(b0) - 1; wbi = wid * 32 + wlane; }
                    else {
                        unsigned b1 = __ballot_sync(FULL, kb == wmax);
                        wlane = __ffs(b1) - 1; wbi = NT + wid * 32 + wlane;
                    }
                    if (lane == wlane) {
                        const float sp_ = (wbi < NT) ? ys[0] : ys[JPT - 1];
                        const float sn_ = (wbi < NT) ? ns[0] : ns[JPT - 1];
                        red[wid] = make_uint4(wmax, (unsigned)wbi,
                                              __float_as_uint(sp_),
                                              __float_as_uint(sn_));
                    }
                    __syncthreads();

                    uint4 best = red[0];
                    #pragma unroll
                    for (int ww = 1; ww < NWARP; ++ww) {
                        uint4 c = red[ww];
                        if (c.x > best.x || (c.x == best.x && c.y < best.y)) best = c;
                    }
                    const float sp = __uint_as_float(best.z);
                    const float sn = __uint_as_float(best.w);
                    float frac = sp / (sp - sn + 1e-12f);
                    frac = fminf(fmaxf(frac, 0.0f), 1.0f);
                    tev = t + frac * dt;
                    #pragma unroll
                    for (int j = 0; j < JPT; ++j) {
                        yv[j] = yv[j] + frac * (nv[j] - yv[j]);
                        yi[j] = yi[j] + frac * (ni[j] - yi[j]);
                        ys[j] = ys[j] + frac * (ns[j] - ys[j]);
                        if (ns[j] > 0.0f) emask |= (1 << j);
                    }
                    trig = true;
                    break;
                }
                #pragma unroll
                for (int j = 0; j < JPT; ++j) { yv[j] = nv[j]; yi[j] = ni[j]; ys[j] = ns[j]; }
                t += dt;
            }
        }

        // ---- outputs (event state = current y) ----
        if (tid == 0) out_times[s * MAXSP + k] = tev;
        const long row = (long)(s * MAXSP + k);
        #pragma unroll
        for (int j = 0; j < JPT; ++j) {
            const int n = tid + j * NT;
            const long base = (row * NN + n) * 3;
            out_vals[base + 0] = yv[j];
            out_vals[base + 1] = yi[j];
            out_vals[base + 2] = ys[j];
            out_marks[row * NN + n] = (emask >> j) & 1 ? 1.0f : 0.0f;
        }

        // ---- next-round state ----
        if (trig) {
            // eidx = first neuron index with event mark (ball[] written pre-barrier;
            // scan order j-major == neuron-index order)
            int eidx = 0;
            #pragma unroll
            for (int q = 0; q < JPT * NWARP; ++q) {
                unsigned bb = ball[q];
                if (bb) { eidx = (q / NWARP) * NT + (q % NWARP) * 32 + __ffs(bb) - 1; break; }
            }
            #pragma unroll
            for (int j = 0; j < JPT; ++j) {
                const int n = tid + j * NT;
                const bool em = (emask >> j) & 1;
                yv[j] = yv[j] - (em ? VRESET : 0.0f);
                yi[j] = yi[j] + w[eidx * NN + n];       // L1 hit via prefetch
                ys[j] = fminf(em ? rs_cur[j] : ys[j], 0.0f);
            }
        } else {
            #pragma unroll
            for (int j = 0; j < JPT; ++j) ys[j] = fminf(ys[j], 0.0f);
        }
        t0s = tev;
        #pragma unroll
        for (int j = 0; j < JPT; ++j) rs_cur[j] = rs_nxt[j];
        // no trailing barrier: the next round's first __syncthreads_or orders
        // all smem reuse
    }
}

extern "C" void kernel_launch(void* const* d_in, const int* in_sizes, int n_in,
                              void* d_out, int out_size) {
    const float* input_current = (const float*)d_in[0];
    const float* w             = (const float*)d_in[1];
    const float* mu            = (const float*)d_in[2];
    const float* v0            = (const float*)d_in[3];
    const float* i0            = (const float*)d_in[4];
    const float* s0            = (const float*)d_in[5];
    const float* reset_s       = (const float*)d_in[6];
    const int*   t1            = (const int*)  d_in[7];

    float* out = (float*)d_out;
    float* out_times = out;                                      // 512*32
    float* out_vals  = out + (long)NS * MAXSP;                   // 512*32*256*3
    float* out_marks = out + (long)NS * MAXSP
                           + (long)NS * MAXSP * NN * 3;          // 512*32*256

    snn_kernel<<<NS, NT>>>(input_current, w, mu, v0, i0, s0, reset_s, t1,
                           out_times, out_vals, out_marks);
}